// round 3
// baseline (speedup 1.0000x reference)
#include <cuda_runtime.h>
#include <cuda_fp16.h>
#include <cstdint>

#define DIMD 1024
#define NB   8
#define SQ   2048
#define SKV  2048

// ---- scratch (device globals; no allocation allowed) ----
__device__ __half g_Xh[(size_t)NB * SQ * DIMD];
__device__ __half g_Ch[(size_t)NB * SKV * DIMD];
__device__ __half g_Wqh[DIMD * DIMD];
__device__ __half g_Wkh[DIMD * DIMD];
__device__ __half g_Wvh[DIMD * DIMD];
__device__ __half g_Qh[(size_t)NB * SQ * DIMD];
__device__ __half g_Kh[(size_t)NB * SKV * DIMD];
__device__ __half g_Vth[(size_t)NB * DIMD * SKV];   // [b][e][t]
__device__ float  g_S[(size_t)NB * SQ * SKV];
__device__ __half g_P[(size_t)NB * SQ * SKV];

// ---- fp32 -> fp16 conversion ----
__global__ void cvt_h_kernel(const float4* __restrict__ in, __half2* __restrict__ out, int n4) {
    int i = blockIdx.x * blockDim.x + threadIdx.x;
    int stride = gridDim.x * blockDim.x;
    for (; i < n4; i += stride) {
        float4 v = in[i];
        out[2 * i]     = __floats2half2_rn(v.x, v.y);
        out[2 * i + 1] = __floats2half2_rn(v.z, v.w);
    }
}

// ================ fp16 TN GEMM: C[M,N] = alpha * A[M,K] * B[N,K]^T ================
// mma.m16n8k16.f32.f16.f16.f32, tile 128x128, BK=32 halves, 4-stage cp.async.
#define BM 128
#define BN 128
#define BKH 32            // halves per k-stage
#define RSTR 80           // smem bytes per row (64 data + 16 pad; all-bank coverage)
#define ASZ (128 * RSTR)  // A block bytes per stage
#define SGB (256 * RSTR)  // full stage bytes (A+B)
#define NST 4
#define SMEMB (NST * SGB) // 81920

__device__ __forceinline__ void cpa16(uint32_t s, const void* g) {
    asm volatile("cp.async.cg.shared.global [%0], [%1], 16;" :: "r"(s), "l"(g));
}

// MODE 0: fp32 store; MODE 1: fp16 store; MODE 2: fp16 transposed store C[n*ldc+m]
template<int MODE>
__global__ __launch_bounds__(256, 2)
void gemm_h(const __half* __restrict__ Ag, const __half* __restrict__ Bg, void* __restrict__ Cv,
            int K, long sA, long sB, long sC, int ldc, float alpha)
{
    extern __shared__ char dsm[];
    const int tid = threadIdx.x, lane = tid & 31, warp = tid >> 5;
    const int m0 = blockIdx.y * BM, n0 = blockIdx.x * BN;
    const __half* A = Ag + (long)blockIdx.z * sA;
    const __half* B = Bg + (long)blockIdx.z * sB;
    const int wm = (warp & 1) * 64, wn = (warp >> 1) * 32;

    uint32_t sb = (uint32_t)__cvta_generic_to_shared(dsm);

    // producer mapping: thread t owns one row (A rows 0..127, B rows 128..255), 4x16B chunks
    const __half* grow = (tid < 128) ? (A + (long)(m0 + tid) * K)
                                     : (B + (long)(n0 + tid - 128) * K);
    const uint32_t smrow = sb + (uint32_t)tid * RSTR;   // A at 0, B naturally at ASZ offset

    float acc[4][4][4];
    #pragma unroll
    for (int i = 0; i < 4; i++)
        #pragma unroll
        for (int j = 0; j < 4; j++) { acc[i][j][0]=0.f; acc[i][j][1]=0.f; acc[i][j][2]=0.f; acc[i][j][3]=0.f; }

    auto issue = [&](int kt, int buf) {
        const __half* g = grow + kt * BKH;
        uint32_t s = smrow + (uint32_t)buf * SGB;
        #pragma unroll
        for (int c = 0; c < 4; ++c) cpa16(s + c * 16u, g + c * 8);
        asm volatile("cp.async.commit_group;");
    };

    // ldmatrix lane address components
    const uint32_t aoff = (uint32_t)((wm + (lane & 15)) * RSTR + ((lane >> 4) & 1) * 16);
    const uint32_t boff = (uint32_t)(ASZ + (wn + (lane & 7)) * RSTR + ((lane >> 3) & 1) * 16);

    const int KT = K >> 5;
    issue(0, 0); issue(1, 1); issue(2, 2);

    for (int kt = 0; kt < KT; ++kt) {
        int buf = kt & 3;
        if (kt + 3 < KT) {
            issue(kt + 3, (kt + 3) & 3);
            asm volatile("cp.async.wait_group 3;");
        } else {
            asm volatile("cp.async.wait_group 0;");
        }
        __syncthreads();
        uint32_t stg = sb + (uint32_t)buf * SGB;
        #pragma unroll
        for (int ks = 0; ks < 2; ++ks) {
            uint32_t a[4][4], b[4][2];
            #pragma unroll
            for (int mt = 0; mt < 4; mt++) {
                uint32_t ad = stg + aoff + (uint32_t)(mt * 16 * RSTR + ks * 32);
                asm volatile("ldmatrix.sync.aligned.m8n8.x4.shared.b16 {%0,%1,%2,%3}, [%4];"
                    : "=r"(a[mt][0]), "=r"(a[mt][1]), "=r"(a[mt][2]), "=r"(a[mt][3]) : "r"(ad));
            }
            #pragma unroll
            for (int nt = 0; nt < 4; nt++) {
                uint32_t bd = stg + boff + (uint32_t)(nt * 8 * RSTR + ks * 32);
                asm volatile("ldmatrix.sync.aligned.m8n8.x2.shared.b16 {%0,%1}, [%2];"
                    : "=r"(b[nt][0]), "=r"(b[nt][1]) : "r"(bd));
            }
            #pragma unroll
            for (int mt = 0; mt < 4; mt++)
                #pragma unroll
                for (int nt = 0; nt < 4; nt++) {
                    asm volatile("mma.sync.aligned.m16n8k16.row.col.f32.f16.f16.f32 "
                        "{%0,%1,%2,%3}, {%4,%5,%6,%7}, {%8,%9}, {%0,%1,%2,%3};"
                        : "+f"(acc[mt][nt][0]), "+f"(acc[mt][nt][1]),
                          "+f"(acc[mt][nt][2]), "+f"(acc[mt][nt][3])
                        : "r"(a[mt][0]), "r"(a[mt][1]), "r"(a[mt][2]), "r"(a[mt][3]),
                          "r"(b[nt][0]), "r"(b[nt][1]));
                }
        }
        __syncthreads();
    }

    // ---- epilogue ----
    const int rr = lane >> 2, cc = (lane & 3) * 2;
    #pragma unroll
    for (int mt = 0; mt < 4; mt++) {
        #pragma unroll
        for (int nt = 0; nt < 4; nt++) {
            int row = m0 + wm + mt * 16 + rr;
            int col = n0 + wn + nt * 8 + cc;
            float v0 = acc[mt][nt][0] * alpha, v1 = acc[mt][nt][1] * alpha;
            float v2 = acc[mt][nt][2] * alpha, v3 = acc[mt][nt][3] * alpha;
            if (MODE == 0) {
                float* C = (float*)Cv + (long)blockIdx.z * sC;
                *reinterpret_cast<float2*>(&C[(long)row       * ldc + col]) = make_float2(v0, v1);
                *reinterpret_cast<float2*>(&C[(long)(row + 8) * ldc + col]) = make_float2(v2, v3);
            } else if (MODE == 1) {
                __half* C = (__half*)Cv + (long)blockIdx.z * sC;
                *reinterpret_cast<__half2*>(&C[(long)row       * ldc + col]) = __floats2half2_rn(v0, v1);
                *reinterpret_cast<__half2*>(&C[(long)(row + 8) * ldc + col]) = __floats2half2_rn(v2, v3);
            } else {
                __half* C = (__half*)Cv + (long)blockIdx.z * sC;
                C[(long)col       * ldc + row    ] = __float2half_rn(v0);
                C[(long)(col + 1) * ldc + row    ] = __float2half_rn(v1);
                C[(long)col       * ldc + row + 8] = __float2half_rn(v2);
                C[(long)(col + 1) * ldc + row + 8] = __float2half_rn(v3);
            }
        }
    }
}

// ---- row softmax over 2048 fp32 cols -> fp16 P ----
__global__ void softmax_kernel(const float* __restrict__ S, __half* __restrict__ P) {
    const float* p = S + (long)blockIdx.x * SKV;
    __half* q = P + (long)blockIdx.x * SKV;
    const int tid = threadIdx.x;  // 256
    float v[8];
    float mx = -3.4e38f;
    #pragma unroll
    for (int i = 0; i < 8; i++) { v[i] = p[tid + (i << 8)]; mx = fmaxf(mx, v[i]); }
    #pragma unroll
    for (int o = 16; o; o >>= 1) mx = fmaxf(mx, __shfl_xor_sync(0xffffffffu, mx, o));
    __shared__ float red[8];
    if ((tid & 31) == 0) red[tid >> 5] = mx;
    __syncthreads();
    float m = red[0];
    #pragma unroll
    for (int i = 1; i < 8; i++) m = fmaxf(m, red[i]);
    float s = 0.f;
    #pragma unroll
    for (int i = 0; i < 8; i++) { v[i] = __expf(v[i] - m); s += v[i]; }
    #pragma unroll
    for (int o = 16; o; o >>= 1) s += __shfl_xor_sync(0xffffffffu, s, o);
    __syncthreads();
    if ((tid & 31) == 0) red[tid >> 5] = s;
    __syncthreads();
    float tot = 0.f;
    #pragma unroll
    for (int i = 0; i < 8; i++) tot += red[i];
    float inv = 1.0f / tot;
    #pragma unroll
    for (int i = 0; i < 8; i++) q[tid + (i << 8)] = __float2half_rn(v[i] * inv);
}

extern "C" void kernel_launch(void* const* d_in, const int* in_sizes, int n_in,
                              void* d_out, int out_size) {
    const float* x  = (const float*)d_in[0];
    const float* cx = (const float*)d_in[1];
    const float* wq = (const float*)d_in[2];
    const float* wk = (const float*)d_in[3];
    const float* wv = (const float*)d_in[4];
    float* out = (float*)d_out;

    __half *pXh, *pCh, *pWq, *pWk, *pWv, *pQ, *pK, *pVt, *pP;
    float *pS;
    cudaGetSymbolAddress((void**)&pXh, g_Xh);
    cudaGetSymbolAddress((void**)&pCh, g_Ch);
    cudaGetSymbolAddress((void**)&pWq, g_Wqh);
    cudaGetSymbolAddress((void**)&pWk, g_Wkh);
    cudaGetSymbolAddress((void**)&pWv, g_Wvh);
    cudaGetSymbolAddress((void**)&pQ,  g_Qh);
    cudaGetSymbolAddress((void**)&pK,  g_Kh);
    cudaGetSymbolAddress((void**)&pVt, g_Vth);
    cudaGetSymbolAddress((void**)&pS,  g_S);
    cudaGetSymbolAddress((void**)&pP,  g_P);

    cudaFuncSetAttribute(gemm_h<0>, cudaFuncAttributeMaxDynamicSharedMemorySize, SMEMB);
    cudaFuncSetAttribute(gemm_h<1>, cudaFuncAttributeMaxDynamicSharedMemorySize, SMEMB);
    cudaFuncSetAttribute(gemm_h<2>, cudaFuncAttributeMaxDynamicSharedMemorySize, SMEMB);

    // 1) convert inputs to fp16
    cvt_h_kernel<<<2048, 256>>>((const float4*)x,  (__half2*)pXh, NB * SQ * DIMD / 4);
    cvt_h_kernel<<<2048, 256>>>((const float4*)cx, (__half2*)pCh, NB * SKV * DIMD / 4);
    cvt_h_kernel<<<512,  256>>>((const float4*)wq, (__half2*)pWq, DIMD * DIMD / 4);
    cvt_h_kernel<<<512,  256>>>((const float4*)wk, (__half2*)pWk, DIMD * DIMD / 4);
    cvt_h_kernel<<<512,  256>>>((const float4*)wv, (__half2*)pWv, DIMD * DIMD / 4);

    // 2) Q = X Wq^T (fp16 store)
    gemm_h<1><<<dim3(DIMD / BN, NB * SQ / BM, 1), 256, SMEMB>>>(
        pXh, pWq, pQ, DIMD, 0, 0, 0, DIMD, 1.f);
    // 3) K = C Wk^T
    gemm_h<1><<<dim3(DIMD / BN, NB * SKV / BM, 1), 256, SMEMB>>>(
        pCh, pWk, pK, DIMD, 0, 0, 0, DIMD, 1.f);
    // 4) Vt[b][e][t] = (C Wv^T)^T  (fp16 transposed store)
    gemm_h<2><<<dim3(DIMD / BN, SKV / BM, NB), 256, SMEMB>>>(
        pCh, pWv, pVt, DIMD, (long)SKV * DIMD, 0, (long)DIMD * SKV, SKV, 1.f);
    // 5) S[b] = Q[b] K[b]^T * D^-0.5  (fp32 store)
    gemm_h<0><<<dim3(SKV / BN, SQ / BM, NB), 256, SMEMB>>>(
        pQ, pK, pS, DIMD, (long)SQ * DIMD, (long)SKV * DIMD, (long)SQ * SKV, SKV, 0.03125f);
    // 6) P = softmax(S)  (fp32 -> fp16)
    softmax_kernel<<<NB * SQ, 256>>>(pS, pP);
    // 7) O[b] = P[b] Vt[b]^T  -> d_out (fp32)
    gemm_h<0><<<dim3(DIMD / BN, SQ / BM, NB), 256, SMEMB>>>(
        pP, pVt, out, SKV, (long)SQ * SKV, (long)DIMD * SKV, (long)SQ * DIMD, DIMD, 1.f);
}

// round 7
// speedup vs baseline: 2.2005x; 2.2005x over previous
#include <cuda_runtime.h>
#include <cuda_fp16.h>
#include <cstdint>

#define DIMD 1024
#define NB   8
#define SQ   2048
#define SKV  2048

// ---- scratch (device globals; no allocation allowed) ----
__device__ __half g_Xh[(size_t)NB * SQ * DIMD];
__device__ __half g_Ch[(size_t)NB * SKV * DIMD];
__device__ __half g_Wqh[DIMD * DIMD];
__device__ __half g_Wkh[DIMD * DIMD];
__device__ __half g_Wvh[DIMD * DIMD];
__device__ __half g_Qh[(size_t)NB * SQ * DIMD];
__device__ __half g_Kh[(size_t)NB * SKV * DIMD];
__device__ __half g_Vth[(size_t)NB * DIMD * SKV];   // [b][e][t]
__device__ float  g_S[(size_t)NB * SQ * SKV];
__device__ __half g_P[(size_t)NB * SQ * SKV];

// ---- fp32 -> fp16 conversion ----
__global__ void cvt_h_kernel(const float4* __restrict__ in, __half2* __restrict__ out, int n4) {
    int i = blockIdx.x * blockDim.x + threadIdx.x;
    int stride = gridDim.x * blockDim.x;
    for (; i < n4; i += stride) {
        float4 v = in[i];
        out[2 * i]     = __floats2half2_rn(v.x, v.y);
        out[2 * i + 1] = __floats2half2_rn(v.z, v.w);
    }
}

// ================ fp16 TN GEMM: C[M,N] = alpha * A[M,K] * B[N,K]^T ================
// Round-1 skeleton, fp16-ized: tile 128x128, BK=32 halves (64B/row), 2-stage cp.async,
// mma.m16n8k16. smem row stride 80B (64 data + 16 pad), static smem, no occupancy forcing.
#define BM 128
#define BN 128
#define BKH 32            // halves per k-stage
#define RSTRB 80          // bytes per smem row
#define STAGEB (BM * RSTRB)   // 10240 bytes per matrix per stage

__device__ __forceinline__ void cpa16(uint32_t s, const void* g) {
    asm volatile("cp.async.cg.shared.global [%0], [%1], 16;" :: "r"(s), "l"(g));
}

// MODE 0: fp32 store; MODE 1: fp16 store; MODE 2: fp16 transposed store C[n*ldc+m]
template<int MODE>
__global__ __launch_bounds__(256)
void gemm_h(const __half* __restrict__ Ag, const __half* __restrict__ Bg, void* __restrict__ Cv,
            int K, long sA, long sB, long sC, int ldc, float alpha)
{
    __shared__ __align__(16) char As[2][STAGEB];
    __shared__ __align__(16) char Bs[2][STAGEB];
    const int tid = threadIdx.x, lane = tid & 31, warp = tid >> 5;
    const int m0 = blockIdx.y * BM, n0 = blockIdx.x * BN;
    const __half* A = Ag + (long)blockIdx.z * sA;
    const __half* B = Bg + (long)blockIdx.z * sB;
    const int wm = (warp & 1) * 64, wn = (warp >> 1) * 32;

    const int lr = tid >> 2;          // 0..63
    const int lcb = (tid & 3) * 16;   // byte col: 0,16,32,48

    uint32_t sA0 = (uint32_t)__cvta_generic_to_shared(&As[0][0]);
    uint32_t sB0 = (uint32_t)__cvta_generic_to_shared(&Bs[0][0]);

    float acc[4][4][4];
    #pragma unroll
    for (int i = 0; i < 4; i++)
        #pragma unroll
        for (int j = 0; j < 4; j++) { acc[i][j][0]=0.f; acc[i][j][1]=0.f; acc[i][j][2]=0.f; acc[i][j][3]=0.f; }

    const __half* aRow0 = A + (long)(m0 + lr)      * K + lcb / 2;
    const __half* aRow1 = A + (long)(m0 + lr + 64) * K + lcb / 2;
    const __half* bRow0 = B + (long)(n0 + lr)      * K + lcb / 2;
    const __half* bRow1 = B + (long)(n0 + lr + 64) * K + lcb / 2;
    uint32_t saw0 = sA0 + (uint32_t)(lr * RSTRB + lcb);
    uint32_t saw1 = sA0 + (uint32_t)((lr + 64) * RSTRB + lcb);
    uint32_t sbw0 = sB0 + (uint32_t)(lr * RSTRB + lcb);
    uint32_t sbw1 = sB0 + (uint32_t)((lr + 64) * RSTRB + lcb);

    auto issue = [&](int kt, int buf) {
        int ko = kt * BKH;
        uint32_t off = (uint32_t)buf * STAGEB;
        cpa16(saw0 + off, aRow0 + ko);
        cpa16(saw1 + off, aRow1 + ko);
        cpa16(sbw0 + off, bRow0 + ko);
        cpa16(sbw1 + off, bRow1 + ko);
        asm volatile("cp.async.commit_group;");
    };

    // ldmatrix lane address components (fp16 m16n8k16 frag recipes; validated round 3)
    const uint32_t aoff = (uint32_t)((wm + (lane & 15)) * RSTRB + ((lane >> 4) & 1) * 16);
    const uint32_t boff = (uint32_t)((wn + (lane & 7)) * RSTRB + ((lane >> 3) & 1) * 16);

    const int KT = K >> 5;
    issue(0, 0);
    for (int kt = 0; kt < KT; ++kt) {
        int buf = kt & 1;
        if (kt + 1 < KT) {
            issue(kt + 1, buf ^ 1);
            asm volatile("cp.async.wait_group 1;");
        } else {
            asm volatile("cp.async.wait_group 0;");
        }
        __syncthreads();
        uint32_t aBase = sA0 + (uint32_t)buf * STAGEB;
        uint32_t bBase = sB0 + (uint32_t)buf * STAGEB;
        #pragma unroll
        for (int ks = 0; ks < 2; ++ks) {
            uint32_t a[4][4], b[4][2];
            #pragma unroll
            for (int mt = 0; mt < 4; mt++) {
                uint32_t ad = aBase + aoff + (uint32_t)(mt * 16 * RSTRB + ks * 32);
                asm volatile("ldmatrix.sync.aligned.m8n8.x4.shared.b16 {%0,%1,%2,%3}, [%4];"
                    : "=r"(a[mt][0]), "=r"(a[mt][1]), "=r"(a[mt][2]), "=r"(a[mt][3]) : "r"(ad));
            }
            #pragma unroll
            for (int nt = 0; nt < 4; nt++) {
                uint32_t bd = bBase + boff + (uint32_t)(nt * 8 * RSTRB + ks * 32);
                asm volatile("ldmatrix.sync.aligned.m8n8.x2.shared.b16 {%0,%1}, [%2];"
                    : "=r"(b[nt][0]), "=r"(b[nt][1]) : "r"(bd));
            }
            #pragma unroll
            for (int mt = 0; mt < 4; mt++)
                #pragma unroll
                for (int nt = 0; nt < 4; nt++) {
                    asm volatile("mma.sync.aligned.m16n8k16.row.col.f32.f16.f16.f32 "
                        "{%0,%1,%2,%3}, {%4,%5,%6,%7}, {%8,%9}, {%0,%1,%2,%3};"
                        : "+f"(acc[mt][nt][0]), "+f"(acc[mt][nt][1]),
                          "+f"(acc[mt][nt][2]), "+f"(acc[mt][nt][3])
                        : "r"(a[mt][0]), "r"(a[mt][1]), "r"(a[mt][2]), "r"(a[mt][3]),
                          "r"(b[nt][0]), "r"(b[nt][1]));
                }
        }
        __syncthreads();
    }

    // ---- epilogue ----
    const int rr = lane >> 2, cc = (lane & 3) * 2;
    #pragma unroll
    for (int mt = 0; mt < 4; mt++) {
        #pragma unroll
        for (int nt = 0; nt < 4; nt++) {
            int row = m0 + wm + mt * 16 + rr;
            int col = n0 + wn + nt * 8 + cc;
            float v0 = acc[mt][nt][0] * alpha, v1 = acc[mt][nt][1] * alpha;
            float v2 = acc[mt][nt][2] * alpha, v3 = acc[mt][nt][3] * alpha;
            if (MODE == 0) {
                float* C = (float*)Cv + (long)blockIdx.z * sC;
                *reinterpret_cast<float2*>(&C[(long)row       * ldc + col]) = make_float2(v0, v1);
                *reinterpret_cast<float2*>(&C[(long)(row + 8) * ldc + col]) = make_float2(v2, v3);
            } else if (MODE == 1) {
                __half* C = (__half*)Cv + (long)blockIdx.z * sC;
                *reinterpret_cast<__half2*>(&C[(long)row       * ldc + col]) = __floats2half2_rn(v0, v1);
                *reinterpret_cast<__half2*>(&C[(long)(row + 8) * ldc + col]) = __floats2half2_rn(v2, v3);
            } else {
                __half* C = (__half*)Cv + (long)blockIdx.z * sC;
                C[(long)col       * ldc + row    ] = __float2half_rn(v0);
                C[(long)(col + 1) * ldc + row    ] = __float2half_rn(v1);
                C[(long)col       * ldc + row + 8] = __float2half_rn(v2);
                C[(long)(col + 1) * ldc + row + 8] = __float2half_rn(v3);
            }
        }
    }
}

// ---- row softmax over 2048 fp32 cols -> fp16 P ----
__global__ void softmax_kernel(const float* __restrict__ S, __half* __restrict__ P) {
    const float* p = S + (long)blockIdx.x * SKV;
    __half* q = P + (long)blockIdx.x * SKV;
    const int tid = threadIdx.x;  // 256
    float v[8];
    float mx = -3.4e38f;
    #pragma unroll
    for (int i = 0; i < 8; i++) { v[i] = p[tid + (i << 8)]; mx = fmaxf(mx, v[i]); }
    #pragma unroll
    for (int o = 16; o; o >>= 1) mx = fmaxf(mx, __shfl_xor_sync(0xffffffffu, mx, o));
    __shared__ float red[8];
    if ((tid & 31) == 0) red[tid >> 5] = mx;
    __syncthreads();
    float m = red[0];
    #pragma unroll
    for (int i = 1; i < 8; i++) m = fmaxf(m, red[i]);
    float s = 0.f;
    #pragma unroll
    for (int i = 0; i < 8; i++) { v[i] = __expf(v[i] - m); s += v[i]; }
    #pragma unroll
    for (int o = 16; o; o >>= 1) s += __shfl_xor_sync(0xffffffffu, s, o);
    __syncthreads();
    if ((tid & 31) == 0) red[tid >> 5] = s;
    __syncthreads();
    float tot = 0.f;
    #pragma unroll
    for (int i = 0; i < 8; i++) tot += red[i];
    float inv = 1.0f / tot;
    #pragma unroll
    for (int i = 0; i < 8; i++) q[tid + (i << 8)] = __float2half_rn(v[i] * inv);
}

extern "C" void kernel_launch(void* const* d_in, const int* in_sizes, int n_in,
                              void* d_out, int out_size) {
    const float* x  = (const float*)d_in[0];
    const float* cx = (const float*)d_in[1];
    const float* wq = (const float*)d_in[2];
    const float* wk = (const float*)d_in[3];
    const float* wv = (const float*)d_in[4];
    float* out = (float*)d_out;

    __half *pXh, *pCh, *pWq, *pWk, *pWv, *pQ, *pK, *pVt, *pP;
    float *pS;
    cudaGetSymbolAddress((void**)&pXh, g_Xh);
    cudaGetSymbolAddress((void**)&pCh, g_Ch);
    cudaGetSymbolAddress((void**)&pWq, g_Wqh);
    cudaGetSymbolAddress((void**)&pWk, g_Wkh);
    cudaGetSymbolAddress((void**)&pWv, g_Wvh);
    cudaGetSymbolAddress((void**)&pQ,  g_Qh);
    cudaGetSymbolAddress((void**)&pK,  g_Kh);
    cudaGetSymbolAddress((void**)&pVt, g_Vth);
    cudaGetSymbolAddress((void**)&pS,  g_S);
    cudaGetSymbolAddress((void**)&pP,  g_P);

    // 1) convert inputs to fp16
    cvt_h_kernel<<<2048, 256>>>((const float4*)x,  (__half2*)pXh, NB * SQ * DIMD / 4);
    cvt_h_kernel<<<2048, 256>>>((const float4*)cx, (__half2*)pCh, NB * SKV * DIMD / 4);
    cvt_h_kernel<<<512,  256>>>((const float4*)wq, (__half2*)pWq, DIMD * DIMD / 4);
    cvt_h_kernel<<<512,  256>>>((const float4*)wk, (__half2*)pWk, DIMD * DIMD / 4);
    cvt_h_kernel<<<512,  256>>>((const float4*)wv, (__half2*)pWv, DIMD * DIMD / 4);

    dim3 blk(256);
    // 2) Q = X Wq^T (fp16 store)
    gemm_h<1><<<dim3(DIMD / BN, NB * SQ / BM, 1), blk>>>(
        pXh, pWq, pQ, DIMD, 0, 0, 0, DIMD, 1.f);
    // 3) K = C Wk^T
    gemm_h<1><<<dim3(DIMD / BN, NB * SKV / BM, 1), blk>>>(
        pCh, pWk, pK, DIMD, 0, 0, 0, DIMD, 1.f);
    // 4) Vt[b][e][t] = (C Wv^T)^T  (fp16 transposed store)
    gemm_h<2><<<dim3(DIMD / BN, SKV / BM, NB), blk>>>(
        pCh, pWv, pVt, DIMD, (long)SKV * DIMD, 0, (long)DIMD * SKV, SKV, 1.f);
    // 5) S[b] = Q[b] K[b]^T * D^-0.5  (fp32 store)
    gemm_h<0><<<dim3(SKV / BN, SQ / BM, NB), blk>>>(
        pQ, pK, pS, DIMD, (long)SQ * DIMD, (long)SKV * DIMD, (long)SQ * SKV, SKV, 0.03125f);
    // 6) P = softmax(S)  (fp32 -> fp16)
    softmax_kernel<<<NB * SQ, 256>>>(pS, pP);
    // 7) O[b] = P[b] Vt[b]^T  -> d_out (fp32)
    gemm_h<0><<<dim3(DIMD / BN, SQ / BM, NB), blk>>>(
        pP, pVt, out, SKV, (long)SQ * SKV, (long)DIMD * SKV, (long)SQ * DIMD, DIMD, 1.f);
}